// round 5
// baseline (speedup 1.0000x reference)
#include <cuda_runtime.h>
#include <math_constants.h>

#define D_FEAT   128
#define K_NEIGH  32
#define WARPS_PER_CTA 4

// Map float -> uint preserving order (monotone), so integer max == float max.
__device__ __forceinline__ unsigned order_key(float f) {
    unsigned x = __float_as_uint(f);
    return (x & 0x80000000u) ? ~x : (x | 0x80000000u);
}

__device__ __forceinline__ unsigned long long pack2(float lo, float hi) {
    unsigned long long r;
    asm("mov.b64 %0, {%1, %2};" : "=l"(r) : "f"(lo), "f"(hi));
    return r;
}
__device__ __forceinline__ void unpack2(unsigned long long p, float& lo, float& hi) {
    asm("mov.b64 {%0, %1}, %2;" : "=f"(lo), "=f"(hi) : "l"(p));
}
__device__ __forceinline__ void fma2(unsigned long long& acc,
                                     unsigned long long a, unsigned long long b) {
    asm("fma.rn.f32x2 %0, %1, %2, %0;" : "+l"(acc) : "l"(a), "l"(b));
}

// One WARP per batch item, no shared memory.
// Sim phase: 4 rows per pass; warp splits into 4 groups of 8 lanes, each group
// owns one row with 128B-contiguous per-instruction chunks (wavefront-optimal
// split — group-of-4 would double row-load wavefronts).
// dot & sumsq accumulate via packed fma.rn.f32x2 on natural register pairs
// ({v.x,v.y}·{c.x,c.y}), halving FMA issue slots and chain depth.
// Ranking key = dot * rsqrt(||n||^2) (center norm cancels for top-k).
// Selection: ns rounds of exact REDUX argmax (tie -> lowest index, matching
// jax.lax.top_k) recorded into a bitmask first; then all winner rows gathered
// back-to-back (MLP=ns, L1/L2-hot) into two accumulators.
__global__ __launch_bounds__(WARPS_PER_CTA * 32, 8)
void intra_agg_kernel(const float*  __restrict__ feats,
                      const int*    __restrict__ nodes,
                      const int*    __restrict__ neighs,
                      const int*    __restrict__ nsamp_p,
                      float*        __restrict__ out)
{
    const int lane = threadIdx.x & 31;
    const int warp = threadIdx.x >> 5;
    const int b    = blockIdx.x * WARPS_PER_CTA + warp;
    const int g    = lane >> 3;        // group 0..3  (which row of the quad)
    const int t    = lane & 7;         // lane within group

    const float4* __restrict__ f4 = reinterpret_cast<const float4*>(feats);

    // ---- center row: this lane's 16-float column slice, pre-packed f32x2 ----
    const int node = nodes[b];
    unsigned long long cxy[4], czw[4];
    #pragma unroll
    for (int j = 0; j < 4; j++) {
        const float4 cv = f4[(size_t)node * (D_FEAT / 4) + t + 8 * j];
        cxy[j] = pack2(cv.x, cv.y);
        czw[j] = pack2(cv.z, cv.w);
    }

    // ---- my neighbor index (one coalesced 128B load) ----
    const int my_idx = neighs[b * K_NEIGH + lane];

    // ---- similarities: 8 passes x 4 rows; lane k ends with sim of row k ----
    float my_sim = 0.0f;
    #pragma unroll
    for (int p = 0; p < K_NEIGH / 4; p++) {
        const int nidx = __shfl_sync(0xffffffffu, my_idx, 4 * p + g);
        const float4* __restrict__ row = f4 + (size_t)nidx * (D_FEAT / 4);

        unsigned long long d2 = 0ull;   // packed {dot_even, dot_odd}
        unsigned long long s2 = 0ull;   // packed {ss_even,  ss_odd }
        #pragma unroll
        for (int j = 0; j < 4; j++) {
            const float4 v = row[t + 8 * j];
            const unsigned long long vxy = pack2(v.x, v.y);
            const unsigned long long vzw = pack2(v.z, v.w);
            fma2(d2, vxy, cxy[j]);
            fma2(d2, vzw, czw[j]);
            fma2(s2, vxy, vxy);
            fma2(s2, vzw, vzw);
        }
        float dl, dh, sl, sh;
        unpack2(d2, dl, dh);
        unpack2(s2, sl, sh);
        float dot = dl + dh;
        float ss  = sl + sh;

        // 3-stage butterfly within each 8-lane group (serves 4 rows at once)
        #pragma unroll
        for (int off = 1; off < 8; off <<= 1) {
            dot += __shfl_xor_sync(0xffffffffu, dot, off);
            ss  += __shfl_xor_sync(0xffffffffu, ss,  off);
        }
        const float s = dot * rsqrtf(ss);
        // route: row 4p+g' was reduced in group g' (lanes 8g'..8g'+7)
        const float sv = __shfl_sync(0xffffffffu, s, (lane & 3) * 8);
        if ((lane >> 2) == p) my_sim = sv;
    }

    const int ns = nsamp_p ? *nsamp_p : 10;

    // ---- top-ns selection: record winners into a bitmask first ----
    unsigned u = order_key(my_sim);
    unsigned wmask = 0u;
    for (int i = 0; i < ns; i++) {
        const unsigned m    = __reduce_max_sync(0xffffffffu, u);
        const unsigned msk  = __ballot_sync(0xffffffffu, u == m);
        const int      w    = __ffs(msk) - 1;           // tie -> lowest index
        if (lane == w) u = 0u;                          // below any real key
        wmask |= 1u << w;
    }

    // ---- gather all winner rows back-to-back (independent loads) ----
    float4 acc0 = make_float4(0.f, 0.f, 0.f, 0.f);
    float4 acc1 = make_float4(0.f, 0.f, 0.f, 0.f);
    int i = 0;
    while (wmask) {
        const int w = __ffs(wmask) - 1;
        wmask &= wmask - 1;
        const int nidx = __shfl_sync(0xffffffffu, my_idx, w);
        const float4 v = f4[(size_t)nidx * (D_FEAT / 4) + lane];
        if (i & 1) { acc1.x += v.x; acc1.y += v.y; acc1.z += v.z; acc1.w += v.w; }
        else       { acc0.x += v.x; acc0.y += v.y; acc0.z += v.z; acc0.w += v.w; }
        i++;
    }

    // ---- mean + relu, coalesced store ----
    const float inv = 1.0f / (float)ns;
    float4 r;
    r.x = fmaxf((acc0.x + acc1.x) * inv, 0.0f);
    r.y = fmaxf((acc0.y + acc1.y) * inv, 0.0f);
    r.z = fmaxf((acc0.z + acc1.z) * inv, 0.0f);
    r.w = fmaxf((acc0.w + acc1.w) * inv, 0.0f);
    reinterpret_cast<float4*>(out)[(size_t)b * (D_FEAT / 4) + lane] = r;
}

extern "C" void kernel_launch(void* const* d_in, const int* in_sizes, int n_in,
                              void* d_out, int out_size)
{
    const float* feats  = (const float*)d_in[0];   // [N_NODES, 128] f32
    const int*   nodes  = (const int*)d_in[1];     // [B] i32
    const int*   neighs = (const int*)d_in[2];     // [B, 32] i32
    const int*   nsamp  = (n_in > 3) ? (const int*)d_in[3] : nullptr;  // scalar (10)

    const int B = in_sizes[1];                     // 32768
    intra_agg_kernel<<<B / WARPS_PER_CTA, WARPS_PER_CTA * 32>>>(
        feats, nodes, neighs, nsamp, (float*)d_out);
}

// round 6
// speedup vs baseline: 1.2243x; 1.2243x over previous
#include <cuda_runtime.h>
#include <math_constants.h>

#define D_FEAT   128
#define K_NEIGH  32
#define WARPS_PER_CTA 4
#define ITEMS_PER_WARP 2

// Map float -> uint preserving order (monotone), so integer max == float max.
__device__ __forceinline__ unsigned order_key(float f) {
    unsigned x = __float_as_uint(f);
    return (x & 0x80000000u) ? ~x : (x | 0x80000000u);
}

// One WARP per TWO batch items, no shared memory. R3's proven math, fused
// across two independent items so their dependency chains overlap:
//  - sim loop: per pass, row 4p+g of item0 AND item1 (8 independent float4
//    loads in flight; 4 butterfly-reduced {dot,ss} pairs share 12 shuffles).
//    Ranking key = dot * rsqrt(||n||^2) (center norm cancels for top-k).
//  - owner permutation: lane 8g+p keeps sim of row 4p+g (kills the route
//    shuffle). Exact-sim ties only occur for duplicate neighbor indices,
//    whose rows are identical, so lane-order tie-break is output-equivalent
//    to jax.lax.top_k's row-order tie-break.
//  - selection: both items' exact REDUX-argmax rounds fused in one loop
//    (two independent latency chains overlap); winner rows re-gathered from
//    global (L1/L2-hot) each round.
__global__ __launch_bounds__(WARPS_PER_CTA * 32, 6)
void intra_agg_kernel(const float*  __restrict__ feats,
                      const int*    __restrict__ nodes,
                      const int*    __restrict__ neighs,
                      const int*    __restrict__ nsamp_p,
                      float*        __restrict__ out)
{
    const int lane = threadIdx.x & 31;
    const int warp = threadIdx.x >> 5;
    const int b0   = (blockIdx.x * WARPS_PER_CTA + warp) * ITEMS_PER_WARP;
    const int b1   = b0 + 1;
    const int g    = lane >> 3;        // group 0..3 (which row of the quad)
    const int t    = lane & 7;         // lane within group

    const float4* __restrict__ f4 = reinterpret_cast<const float4*>(feats);

    // ---- center rows: this lane's 16-float column slice of each center ----
    const int node0 = nodes[b0];
    const int node1 = nodes[b1];
    float4 c0[4], c1[4];
    #pragma unroll
    for (int j = 0; j < 4; j++) {
        c0[j] = f4[(size_t)node0 * (D_FEAT / 4) + t + 8 * j];
        c1[j] = f4[(size_t)node1 * (D_FEAT / 4) + t + 8 * j];
    }

    // ---- neighbor indices (lane k holds index k of each item) ----
    const int idx0 = neighs[b0 * K_NEIGH + lane];
    const int idx1 = neighs[b1 * K_NEIGH + lane];

    // ---- similarities: 8 passes; pass p handles row 4p+g of BOTH items ----
    // Owner permutation: lane 8g+p (i.e. t==p within group g) keeps row 4p+g.
    float sim0 = 0.0f, sim1 = 0.0f;
    #pragma unroll
    for (int p = 0; p < K_NEIGH / 4; p++) {
        const int n0 = __shfl_sync(0xffffffffu, idx0, 4 * p + g);
        const int n1 = __shfl_sync(0xffffffffu, idx1, 4 * p + g);
        const float4* __restrict__ r0 = f4 + (size_t)n0 * (D_FEAT / 4);
        const float4* __restrict__ r1 = f4 + (size_t)n1 * (D_FEAT / 4);

        float d0 = 0.f, s0 = 0.f, d1 = 0.f, s1 = 0.f;
        #pragma unroll
        for (int j = 0; j < 4; j++) {
            const float4 v = r0[t + 8 * j];
            d0 = fmaf(v.x, c0[j].x, fmaf(v.y, c0[j].y,
                 fmaf(v.z, c0[j].z, fmaf(v.w, c0[j].w, d0))));
            s0 = fmaf(v.x, v.x, fmaf(v.y, v.y,
                 fmaf(v.z, v.z, fmaf(v.w, v.w, s0))));
            const float4 w = r1[t + 8 * j];
            d1 = fmaf(w.x, c1[j].x, fmaf(w.y, c1[j].y,
                 fmaf(w.z, c1[j].z, fmaf(w.w, c1[j].w, d1))));
            s1 = fmaf(w.x, w.x, fmaf(w.y, w.y,
                 fmaf(w.z, w.z, fmaf(w.w, w.w, s1))));
        }
        // 3-stage butterfly within each 8-lane group; 12 shuffles serve the
        // 8 rows (4 per item) of this pass.
        #pragma unroll
        for (int off = 1; off < 8; off <<= 1) {
            d0 += __shfl_xor_sync(0xffffffffu, d0, off);
            s0 += __shfl_xor_sync(0xffffffffu, s0, off);
            d1 += __shfl_xor_sync(0xffffffffu, d1, off);
            s1 += __shfl_xor_sync(0xffffffffu, s1, off);
        }
        if (t == p) {
            sim0 = d0 * rsqrtf(s0);
            sim1 = d1 * rsqrtf(s1);
        }
    }

    const int ns = nsamp_p ? *nsamp_p : 10;

    // ---- fused top-ns selection + gather for both items ----
    unsigned u0 = order_key(sim0);
    unsigned u1 = order_key(sim1);
    float4 acc0 = make_float4(0.f, 0.f, 0.f, 0.f);
    float4 acc1 = make_float4(0.f, 0.f, 0.f, 0.f);
    for (int i = 0; i < ns; i++) {
        const unsigned m0  = __reduce_max_sync(0xffffffffu, u0);
        const unsigned m1  = __reduce_max_sync(0xffffffffu, u1);
        const unsigned bm0 = __ballot_sync(0xffffffffu, u0 == m0);
        const unsigned bm1 = __ballot_sync(0xffffffffu, u1 == m1);
        const int w0 = __ffs(bm0) - 1;                 // winner owner lane
        const int w1 = __ffs(bm1) - 1;
        if (lane == w0) u0 = 0u;                       // remove winner
        if (lane == w1) u1 = 0u;
        // owner lane 8g+p  ->  row 4p+g
        const int row0 = 4 * (w0 & 7) + (w0 >> 3);
        const int row1 = 4 * (w1 & 7) + (w1 >> 3);
        const int nn0 = __shfl_sync(0xffffffffu, idx0, row0);
        const int nn1 = __shfl_sync(0xffffffffu, idx1, row1);
        const float4 v0 = f4[(size_t)nn0 * (D_FEAT / 4) + lane];
        const float4 v1 = f4[(size_t)nn1 * (D_FEAT / 4) + lane];
        acc0.x += v0.x; acc0.y += v0.y; acc0.z += v0.z; acc0.w += v0.w;
        acc1.x += v1.x; acc1.y += v1.y; acc1.z += v1.z; acc1.w += v1.w;
    }

    // ---- mean + relu, coalesced stores ----
    const float inv = 1.0f / (float)ns;
    float4 r0v, r1v;
    r0v.x = fmaxf(acc0.x * inv, 0.0f);
    r0v.y = fmaxf(acc0.y * inv, 0.0f);
    r0v.z = fmaxf(acc0.z * inv, 0.0f);
    r0v.w = fmaxf(acc0.w * inv, 0.0f);
    r1v.x = fmaxf(acc1.x * inv, 0.0f);
    r1v.y = fmaxf(acc1.y * inv, 0.0f);
    r1v.z = fmaxf(acc1.z * inv, 0.0f);
    r1v.w = fmaxf(acc1.w * inv, 0.0f);
    reinterpret_cast<float4*>(out)[(size_t)b0 * (D_FEAT / 4) + lane] = r0v;
    reinterpret_cast<float4*>(out)[(size_t)b1 * (D_FEAT / 4) + lane] = r1v;
}

extern "C" void kernel_launch(void* const* d_in, const int* in_sizes, int n_in,
                              void* d_out, int out_size)
{
    const float* feats  = (const float*)d_in[0];   // [N_NODES, 128] f32
    const int*   nodes  = (const int*)d_in[1];     // [B] i32
    const int*   neighs = (const int*)d_in[2];     // [B, 32] i32
    const int*   nsamp  = (n_in > 3) ? (const int*)d_in[3] : nullptr;  // scalar (10)

    const int B = in_sizes[1];                     // 32768
    intra_agg_kernel<<<B / (WARPS_PER_CTA * ITEMS_PER_WARP), WARPS_PER_CTA * 32>>>(
        feats, nodes, neighs, nsamp, (float*)d_out);
}